// round 2
// baseline (speedup 1.0000x reference)
#include <cuda_runtime.h>
#include <math.h>

#define C 128
#define H 256
#define W 256
#define HW (H*W)

// ---------------- scratch (no allocations allowed) ----------------
__device__ float g_mean[C];
__device__ float g_std[C];
__device__ float g_rstd[C];
__device__ float g_AY[C][H][4];   // Wy-contracted mean patch per (c, row)
__device__ float g_BY[C][H][4];   // Wy-contracted 1/std patch per (c, row)
__device__ float g_WX[W][4];      // bicubic row-stochastic weight rows (h==w so shared)

// ---------------- kernel A: per-channel mean / unbiased std of pre half ----------------
__global__ __launch_bounds__(1024) void reduce_kernel(const float* __restrict__ x) {
    int c = blockIdx.x;
    const float4* p = (const float4*)(x + (size_t)(C + c) * HW);  // batch 1 = pre
    int t = threadIdx.x;
    float s = 0.f, ss = 0.f;
#pragma unroll
    for (int k = 0; k < HW / 4 / 1024; ++k) {        // 16 float4 per thread
        float4 v = p[t + k * 1024];
        s  += v.x + v.y + v.z + v.w;
        ss += v.x * v.x + v.y * v.y + v.z * v.z + v.w * v.w;
    }
    __shared__ float sh_s[32], sh_ss[32];
#pragma unroll
    for (int off = 16; off; off >>= 1) {
        s  += __shfl_down_sync(0xFFFFFFFFu, s, off);
        ss += __shfl_down_sync(0xFFFFFFFFu, ss, off);
    }
    int wrp = t >> 5, lane = t & 31;
    if (lane == 0) { sh_s[wrp] = s; sh_ss[wrp] = ss; }
    __syncthreads();
    if (wrp == 0) {
        s  = sh_s[lane];
        ss = sh_ss[lane];
#pragma unroll
        for (int off = 16; off; off >>= 1) {
            s  += __shfl_down_sync(0xFFFFFFFFu, s, off);
            ss += __shfl_down_sync(0xFFFFFFFFu, ss, off);
        }
        if (lane == 0) {
            float mean = s * (1.0f / (float)HW);
            float var  = fmaxf((ss - s * mean) * (1.0f / (float)(HW - 1)), 0.f);
            float sd   = sqrtf(var);
            g_mean[c] = mean;
            g_std[c]  = sd;
            g_rstd[c] = 1.0f / sd;
        }
    }
}

// ---------------- bicubic helpers (PyTorch a=-0.75 kernel) ----------------
__device__ __forceinline__ float cubicw(float t) {
    float at = fabsf(t);
    float nearv = (1.25f * at - 2.25f) * at * at + 1.0f;            // (a+2)|t|^3-(a+3)|t|^2+1
    float farv  = (((at - 5.0f) * at + 8.0f) * at - 4.0f) * -0.75f; // a(|t|^3-5|t|^2+8|t|-4)
    return (at <= 1.0f) ? nearv : ((at < 2.0f) ? farv : 0.0f);
}

// Effective row of the row-stochastic (out,4) matrix after clamped scatter-add.
// Row index in the full (3h,4) matrix is o + h/2 (center crop folded in).
__device__ __forceinline__ void wrow(int o, float wf[4]) {
    float src = ((float)(o + H / 2) + 0.5f) * (4.0f / (3.0f * (float)H)) - 0.5f;
    float fi0 = floorf(src);
    float t = src - fi0;
    int i0 = (int)fi0;
    wf[0] = wf[1] = wf[2] = wf[3] = 0.f;
#pragma unroll
    for (int j = 0; j < 4; ++j) {
        float wv = cubicw(t - (float)(j - 1));
        int idx = i0 + (j - 1);
        idx = min(max(idx, 0), 3);
        wf[idx] += wv;
    }
}

// ---------------- kernel B: patch gather + Y-contraction ----------------
__global__ __launch_bounds__(256) void prep_kernel(
    const float* __restrict__ mean_table, const float* __restrict__ std_table,
    const int* __restrict__ yap, const int* __restrict__ xap,
    const int* __restrict__ pyp, const int* __restrict__ pxp) {
    int c = blockIdx.x;
    int t = threadIdx.x;
    __shared__ float sm[16], si[16];

    int ya = min(max(yap[0], 0), 15);   // dynamic_slice start clamp (19-4=15)
    int xa = min(max(xap[0], 0), 15);
    int pyy = pyp[0], pxx = pxp[0];

    if (t < 16) {
        int dy = t >> 2, dx = t & 3;
        int oy = min(max(ya + dy - 1, 0), 15);  // edge pad (top=1) -> clamp
        int ox = min(max(xa + dx - 1, 0), 15);
        float m, sd;
        if (oy == pyy && ox == pxx) { m = g_mean[c]; sd = g_std[c]; }
        else {
            m  = mean_table[(oy * 16 + ox) * C + c];
            sd = std_table[(oy * 16 + ox) * C + c];
        }
        sm[t] = m;
        si[t] = 1.0f / sd;
    }
    __syncthreads();

    float wf[4];
    wrow(t, wf);   // one output row per thread (t = 0..255)
    float ay[4], by[4];
#pragma unroll
    for (int xx = 0; xx < 4; ++xx) {
        float a = 0.f, b = 0.f;
#pragma unroll
        for (int y = 0; y < 4; ++y) {
            a = fmaf(wf[y], sm[y * 4 + xx], a);
            b = fmaf(wf[y], si[y * 4 + xx], b);
        }
        ay[xx] = a; by[xx] = b;
    }
    ((float4*)g_AY)[c * H + t] = make_float4(ay[0], ay[1], ay[2], ay[3]);
    ((float4*)g_BY)[c * H + t] = make_float4(by[0], by[1], by[2], by[3]);
    if (c == 0)
        ((float4*)g_WX)[t] = make_float4(wf[0], wf[1], wf[2], wf[3]);  // h==w -> same table
}

// ---------------- kernel C: main normalization pass (both halves) ----------------
__global__ __launch_bounds__(256) void norm_kernel(
    const float* __restrict__ x, const float* __restrict__ wt,
    const float* __restrict__ bs, float* __restrict__ out) {
    int c = blockIdx.y;
    int o = blockIdx.x * 4 + (threadIdx.x >> 6);   // output row
    int q = threadIdx.x & 63;                      // float4 group within row

    size_t rbase = ((size_t)c * H + o) * W;
    const float4* xr  = (const float4*)(x + rbase);
    const float4* xp  = (const float4*)(x + rbase + (size_t)C * HW);
    float4* outr = (float4*)(out + rbase);
    float4* outp = (float4*)(out + rbase + (size_t)C * HW);

    float4 ay = ((const float4*)g_AY)[c * H + o];  // broadcast within row group
    float4 by = ((const float4*)g_BY)[c * H + o];
    float wc = wt[c], bc = bs[c];
    float ps = g_rstd[c] * wc;                     // pre-half fused scale
    float po = fmaf(-g_mean[c], ps, bc);           // pre-half fused offset

    float4 vr = xr[q];
    float4 vp = xp[q];
    float inr[4] = {vr.x, vr.y, vr.z, vr.w};
    float inp[4] = {vp.x, vp.y, vp.z, vp.w};
    float orr[4], opp[4];

    const float4* WX = (const float4*)g_WX;
#pragma unroll
    for (int j = 0; j < 4; ++j) {
        float4 w = WX[4 * q + j];                  // pixel p = 4q+j
        float mean = w.x * ay.x + w.y * ay.y + w.z * ay.z + w.w * ay.w;
        float inv  = w.x * by.x + w.y * by.y + w.z * by.z + w.w * by.w;
        orr[j] = fmaf((inr[j] - mean) * inv, wc, bc);
        opp[j] = fmaf(inp[j], ps, po);
    }
    outr[q] = make_float4(orr[0], orr[1], orr[2], orr[3]);
    outp[q] = make_float4(opp[0], opp[1], opp[2], opp[3]);
}

// ---------------- launch ----------------
extern "C" void kernel_launch(void* const* d_in, const int* in_sizes, int n_in,
                              void* d_out, int out_size) {
    const float* x          = (const float*)d_in[0];
    const float* mean_table = (const float*)d_in[1];
    const float* std_table  = (const float*)d_in[2];
    const float* weight     = (const float*)d_in[3];
    const float* bias       = (const float*)d_in[4];
    const int*   y_anchor   = (const int*)d_in[5];
    const int*   x_anchor   = (const int*)d_in[6];
    const int*   pre_y1     = (const int*)d_in[7];
    const int*   pre_x1     = (const int*)d_in[8];
    float* out = (float*)d_out;

    reduce_kernel<<<C, 1024>>>(x);
    prep_kernel<<<C, 256>>>(mean_table, std_table, y_anchor, x_anchor, pre_y1, pre_x1);
    norm_kernel<<<dim3(H / 4, C), 256>>>(x, weight, bias, out);
}